// round 1
// baseline (speedup 1.0000x reference)
#include <cuda_runtime.h>
#include <math.h>

#define CBN   6
#define CSZ   1024
#define CDIM  8
#define TPB   256
#define NW    8            // warps per CTA
#define CPW   (CSZ / NW)   // candidates per warp = 128
#define RPT   8            // rows per thread
#define ROWS  256          // rows per CTA (32 lanes * RPT)

// scratch for deterministic bits reduction (allocation-free: __device__ global)
__device__ float g_logp[32768 * CBN];

struct Smem {
    float4 cA[CSZ];            // c[0..3]
    float4 cB[CSZ];            // c[4..7]
    float2 meta[CSZ];          // (c2, L = log2pmf/lambda)
    float  xsh[ROWS * CDIM];   // x tile
    float2 red[NW * ROWS];     // per-warp (best, idx) partials; reused as scratch
};

__device__ __forceinline__ float sqrt_approx(float v) {
    float r;
    asm("sqrt.approx.f32 %0, %1;" : "=f"(r) : "f"(v));
    return r;
}

__global__ void __launch_bounds__(TPB) ecvq_kernel(
    const float* __restrict__ x,
    const float* __restrict__ codebook,
    const float* __restrict__ logits,
    float* __restrict__ out,
    int B)
{
    extern __shared__ unsigned char smem_raw[];
    Smem* sm = reinterpret_cast<Smem*>(smem_raw);

    const int tid     = threadIdx.x;
    const int cb      = blockIdx.x;
    const int rowBase = blockIdx.y * ROWS;
    float* scratch = reinterpret_cast<float*>(sm->red);

    // ---- log-softmax over logits[cb][:], L[s] = -log_softmax * (1/ln2) / lambda ----
    float4 lv = *reinterpret_cast<const float4*>(logits + (size_t)cb * CSZ + tid * 4);
    float lm = fmaxf(fmaxf(lv.x, lv.y), fmaxf(lv.z, lv.w));
    scratch[tid] = lm; __syncthreads();
    #pragma unroll
    for (int off = 128; off > 0; off >>= 1) {
        if (tid < off) scratch[tid] = fmaxf(scratch[tid], scratch[tid + off]);
        __syncthreads();
    }
    const float m = scratch[0]; __syncthreads();
    float es = expf(lv.x - m) + expf(lv.y - m) + expf(lv.z - m) + expf(lv.w - m);
    scratch[tid] = es; __syncthreads();
    #pragma unroll
    for (int off = 128; off > 0; off >>= 1) {
        if (tid < off) scratch[tid] += scratch[tid + off];
        __syncthreads();
    }
    const float lnS = logf(scratch[0]); __syncthreads();

    // ---- stage codebook slice: raw c values, c2, L ----
    const float INV_LOG2 = 1.4426950408889634f;
    #pragma unroll
    for (int j = 0; j < 4; j++) {
        int s = tid * 4 + j;
        const float4* cp = reinterpret_cast<const float4*>(
            codebook + ((size_t)cb * CSZ + s) * CDIM);
        float4 c0 = cp[0], c1 = cp[1];
        // c2: squares then sequential adds (mimic reduce semantics)
        float q0 = c0.x * c0.x, q1 = c0.y * c0.y, q2 = c0.z * c0.z, q3 = c0.w * c0.w;
        float q4 = c1.x * c1.x, q5 = c1.y * c1.y, q6 = c1.z * c1.z, q7 = c1.w * c1.w;
        float c2 = ((((((q0 + q1) + q2) + q3) + q4) + q5) + q6) + q7;
        float v = (j == 0) ? lv.x : (j == 1) ? lv.y : (j == 2) ? lv.z : lv.w;
        float sh = v - m;                 // match jax log_softmax structure
        float ls = sh - lnS;
        float p2 = ls * (-INV_LOG2);      // log2_pmf
        float L  = p2 / 0.005f;           // divide by the same fp32 constant as ref
        sm->cA[s]   = c0;
        sm->cB[s]   = c1;
        sm->meta[s] = make_float2(c2, L);
    }

    // ---- stage x tile (one row per thread, this cb's 8-float slice) ----
    {
        int row = rowBase + tid;
        const float4* xp = reinterpret_cast<const float4*>(
            x + (size_t)row * (CBN * CDIM) + cb * CDIM);
        float4 p0 = xp[0], p1 = xp[1];
        float4* d = reinterpret_cast<float4*>(&sm->xsh[tid * CDIM]);
        d[0] = p0; d[1] = p1;
    }
    __syncthreads();

    // ---- per-thread registers: 8 rows ----
    const int lane = tid & 31, warp = tid >> 5;
    float xv[RPT][CDIM];
    float x2v[RPT], best[RPT];
    int   bidx[RPT];
    #pragma unroll
    for (int i = 0; i < RPT; i++) {
        const float4* p = reinterpret_cast<const float4*>(
            &sm->xsh[(i * 32 + lane) * CDIM]);
        float4 a = p[0], b = p[1];
        xv[i][0] = a.x; xv[i][1] = a.y; xv[i][2] = a.z; xv[i][3] = a.w;
        xv[i][4] = b.x; xv[i][5] = b.y; xv[i][6] = b.z; xv[i][7] = b.w;
        float q0 = a.x*a.x, q1 = a.y*a.y, q2 = a.z*a.z, q3 = a.w*a.w;
        float q4 = b.x*b.x, q5 = b.y*b.y, q6 = b.z*b.z, q7 = b.w*b.w;
        x2v[i] = ((((((q0 + q1) + q2) + q3) + q4) + q5) + q6) + q7;
        best[i] = __int_as_float(0x7f800000);  // +inf
        bidx[i] = 0;
    }

    // ---- main scan: this warp covers candidates [warp*128, warp*128+128) ----
    const int s0 = warp * CPW;
    #pragma unroll 2
    for (int t = 0; t < CPW; t++) {
        const int s = s0 + t;
        const float4 a  = sm->cA[s];
        const float4 b  = sm->cB[s];
        const float2 mt = sm->meta[s];
        #pragma unroll
        for (int i = 0; i < RPT; i++) {
            // dot ascending k (fma chain), then (x2 - 2*xc) + c2 like reference
            float xc = xv[i][0] * a.x;
            xc = fmaf(xv[i][1], a.y, xc);
            xc = fmaf(xv[i][2], a.z, xc);
            xc = fmaf(xv[i][3], a.w, xc);
            xc = fmaf(xv[i][4], b.x, xc);
            xc = fmaf(xv[i][5], b.y, xc);
            xc = fmaf(xv[i][6], b.z, xc);
            xc = fmaf(xv[i][7], b.w, xc);
            float d2 = fmaf(-2.0f, xc, x2v[i]) + mt.x;
            float val = sqrt_approx(fmaxf(d2, 0.0f)) + mt.y;
            if (val < best[i]) { best[i] = val; bidx[i] = s; }
        }
    }

    // ---- cross-warp argmin reduce (ascending warp order == ascending s) ----
    #pragma unroll
    for (int i = 0; i < RPT; i++)
        sm->red[warp * ROWS + i * 32 + lane] =
            make_float2(best[i], __int_as_float(bidx[i]));
    __syncthreads();

    {
        float bc = __int_as_float(0x7f800000);
        int   bi = 0;
        #pragma unroll
        for (int w = 0; w < NW; w++) {
            float2 c = sm->red[w * ROWS + tid];
            int ci = __float_as_int(c.y);
            if (c.x < bc) { bc = c.x; bi = ci; }   // strict <: keeps first (lowest s)
        }
        const int grow = rowBase + tid;
        // x_hat = codebook row (exact bits, staged raw in smem)
        float4 h0 = sm->cA[bi];
        float4 h1 = sm->cB[bi];
        float4* op = reinterpret_cast<float4*>(
            out + (size_t)grow * (CBN * CDIM) + cb * CDIM);
        op[0] = h0; op[1] = h1;
        // index block (after x_hat block and the single bits element)
        out[(size_t)B * (CBN * CDIM) + 1 + (size_t)grow * CBN + cb] = (float)bi;
        // per-(row,cb) log2_prob for deterministic bits reduction
        g_logp[(size_t)grow * CBN + cb] = sm->meta[bi].y * 0.005f;
    }
}

// Deterministic bits reduction: fixed-order strided double accumulation + tree.
__global__ void __launch_bounds__(256) bits_kernel(float* __restrict__ out_bits, int n)
{
    __shared__ double sd[256];
    double acc = 0.0;
    for (int i = threadIdx.x; i < n; i += 256)
        acc += (double)g_logp[i];
    sd[threadIdx.x] = acc;
    __syncthreads();
    #pragma unroll
    for (int off = 128; off > 0; off >>= 1) {
        if (threadIdx.x < off) sd[threadIdx.x] += sd[threadIdx.x + off];
        __syncthreads();
    }
    if (threadIdx.x == 0) *out_bits = (float)sd[0];
}

extern "C" void kernel_launch(void* const* d_in, const int* in_sizes, int n_in,
                              void* d_out, int out_size)
{
    // Identify inputs by element count (robust to ordering):
    //   logits   = 6*1024       = 6144
    //   codebook = 6*1024*8     = 49152
    //   x        = everything else (B*48)
    const float* x = nullptr;
    const float* codebook = nullptr;
    const float* logits = nullptr;
    for (int i = 0; i < n_in; i++) {
        if (in_sizes[i] == CBN * CSZ)            logits   = (const float*)d_in[i];
        else if (in_sizes[i] == CBN * CSZ * CDIM) codebook = (const float*)d_in[i];
        else                                      x        = (const float*)d_in[i];
    }
    float* out = (float*)d_out;
    int B = 0;
    for (int i = 0; i < n_in; i++)
        if ((const float*)d_in[i] == x) B = in_sizes[i] / (CBN * CDIM);

    size_t smem = sizeof(Smem);
    cudaFuncSetAttribute(ecvq_kernel,
                         cudaFuncAttributeMaxDynamicSharedMemorySize, (int)smem);

    dim3 grid(CBN, B / ROWS);
    ecvq_kernel<<<grid, TPB, smem>>>(x, codebook, logits, out, B);
    bits_kernel<<<1, 256>>>(out + (size_t)B * (CBN * CDIM), B * CBN);
}

// round 2
// speedup vs baseline: 1.5650x; 1.5650x over previous
#include <cuda_runtime.h>
#include <math.h>

#define CBN   6
#define CSZ   1024
#define CDIM  8
#define TPB   256
#define NW    8
#define CPW   (CSZ / NW)     // 128 candidates per warp
#define NPAIR 4              // row pairs per thread (8 rows)
#define ROWS  256            // rows per CTA

typedef unsigned long long u64;

// per-CTA double partial sums for deterministic bits reduction
__device__ double g_part[128 * CBN];

struct Smem {
    ulonglong2 cdup[CSZ * 4];   // 64KB: per s, dims (k,k+1) duplicated: ((ck,ck),(ck+1,ck+1))
    ulonglong2 meta[CSZ];       // 16KB: ((c2,c2),(L,L))
    float      p2sh[CSZ];       //  4KB: log2_pmf per candidate
    float      xsh[ROWS * CDIM];//  8KB
    float2     red[NW * ROWS];  // 16KB: cross-warp argmin partials (also reused scratch)
};

__device__ __forceinline__ u64 pack2(float lo, float hi) {
    u64 r; asm("mov.b64 %0, {%1,%2};" : "=l"(r) : "f"(lo), "f"(hi)); return r;
}
__device__ __forceinline__ void unpack2(float& lo, float& hi, u64 v) {
    asm("mov.b64 {%0,%1}, %2;" : "=f"(lo), "=f"(hi) : "l"(v));
}
__device__ __forceinline__ u64 mul2(u64 a, u64 b) {
    u64 d; asm("mul.rn.f32x2 %0, %1, %2;" : "=l"(d) : "l"(a), "l"(b)); return d;
}
__device__ __forceinline__ u64 add2(u64 a, u64 b) {
    u64 d; asm("add.rn.f32x2 %0, %1, %2;" : "=l"(d) : "l"(a), "l"(b)); return d;
}
__device__ __forceinline__ u64 fma2(u64 a, u64 b, u64 c) {
    u64 d; asm("fma.rn.f32x2 %0, %1, %2, %3;" : "=l"(d) : "l"(a), "l"(b), "l"(c)); return d;
}
__device__ __forceinline__ float sqrt_approx(float v) {
    float r; asm("sqrt.approx.f32 %0, %1;" : "=f"(r) : "f"(v)); return r;
}

__global__ void __launch_bounds__(TPB, 2) ecvq_kernel(
    const float* __restrict__ x,
    const float* __restrict__ codebook,
    const float* __restrict__ logits,
    float* __restrict__ out,
    int B)
{
    extern __shared__ unsigned char smem_raw[];
    Smem* sm = reinterpret_cast<Smem*>(smem_raw);

    const int tid     = threadIdx.x;
    const int cb      = blockIdx.x;
    const int rowBase = blockIdx.y * ROWS;
    float* scratch = reinterpret_cast<float*>(sm->red);

    // ---- log-softmax over logits[cb][:] ----
    float4 lv = *reinterpret_cast<const float4*>(logits + (size_t)cb * CSZ + tid * 4);
    float lm = fmaxf(fmaxf(lv.x, lv.y), fmaxf(lv.z, lv.w));
    scratch[tid] = lm; __syncthreads();
    #pragma unroll
    for (int off = 128; off > 0; off >>= 1) {
        if (tid < off) scratch[tid] = fmaxf(scratch[tid], scratch[tid + off]);
        __syncthreads();
    }
    const float m = scratch[0]; __syncthreads();
    float es = expf(lv.x - m) + expf(lv.y - m) + expf(lv.z - m) + expf(lv.w - m);
    scratch[tid] = es; __syncthreads();
    #pragma unroll
    for (int off = 128; off > 0; off >>= 1) {
        if (tid < off) scratch[tid] += scratch[tid + off];
        __syncthreads();
    }
    const float lnS = logf(scratch[0]); __syncthreads();

    // ---- stage codebook slice (duplicated for packed math) ----
    const float INV_LOG2 = 1.4426950408889634f;
    #pragma unroll
    for (int j = 0; j < 4; j++) {
        int s = tid * 4 + j;
        const float4* cp = reinterpret_cast<const float4*>(
            codebook + ((size_t)cb * CSZ + s) * CDIM);
        float4 c0 = cp[0], c1 = cp[1];
        float q0 = c0.x*c0.x, q1 = c0.y*c0.y, q2 = c0.z*c0.z, q3 = c0.w*c0.w;
        float q4 = c1.x*c1.x, q5 = c1.y*c1.y, q6 = c1.z*c1.z, q7 = c1.w*c1.w;
        float c2 = ((((((q0 + q1) + q2) + q3) + q4) + q5) + q6) + q7;
        float v  = (j == 0) ? lv.x : (j == 1) ? lv.y : (j == 2) ? lv.z : lv.w;
        float p2 = ((v - m) - lnS) * (-INV_LOG2);   // log2_pmf
        float L  = p2 / 0.005f;
        sm->cdup[4*s+0] = make_ulonglong2(pack2(c0.x, c0.x), pack2(c0.y, c0.y));
        sm->cdup[4*s+1] = make_ulonglong2(pack2(c0.z, c0.z), pack2(c0.w, c0.w));
        sm->cdup[4*s+2] = make_ulonglong2(pack2(c1.x, c1.x), pack2(c1.y, c1.y));
        sm->cdup[4*s+3] = make_ulonglong2(pack2(c1.z, c1.z), pack2(c1.w, c1.w));
        sm->meta[s]     = make_ulonglong2(pack2(c2, c2), pack2(L, L));
        sm->p2sh[s]     = p2;
    }

    // ---- stage x tile ----
    {
        int row = rowBase + tid;
        const float4* xp = reinterpret_cast<const float4*>(
            x + (size_t)row * (CBN * CDIM) + cb * CDIM);
        float4 p0 = xp[0], p1 = xp[1];
        float4* d = reinterpret_cast<float4*>(&sm->xsh[tid * CDIM]);
        d[0] = p0; d[1] = p1;
    }
    __syncthreads();

    // ---- per-thread registers: 4 row-pairs (8 rows), packed ----
    const int lane = tid & 31, warp = tid >> 5;
    u64   xp[NPAIR][CDIM];
    u64   x2p[NPAIR];
    float best[2 * NPAIR];
    int   bidx[2 * NPAIR];
    #pragma unroll
    for (int p = 0; p < NPAIR; p++) {
        int rA = (2 * p) * 32 + lane;
        int rB = rA + 32;
        const float4* pa = reinterpret_cast<const float4*>(&sm->xsh[rA * CDIM]);
        const float4* pb = reinterpret_cast<const float4*>(&sm->xsh[rB * CDIM]);
        float4 a0 = pa[0], a1 = pa[1];
        float4 b0 = pb[0], b1 = pb[1];
        xp[p][0] = pack2(a0.x, b0.x); xp[p][1] = pack2(a0.y, b0.y);
        xp[p][2] = pack2(a0.z, b0.z); xp[p][3] = pack2(a0.w, b0.w);
        xp[p][4] = pack2(a1.x, b1.x); xp[p][5] = pack2(a1.y, b1.y);
        xp[p][6] = pack2(a1.z, b1.z); xp[p][7] = pack2(a1.w, b1.w);
        float xA = ((((((a0.x*a0.x + a0.y*a0.y) + a0.z*a0.z) + a0.w*a0.w)
                      + a1.x*a1.x) + a1.y*a1.y) + a1.z*a1.z) + a1.w*a1.w;
        float xB = ((((((b0.x*b0.x + b0.y*b0.y) + b0.z*b0.z) + b0.w*b0.w)
                      + b1.x*b1.x) + b1.y*b1.y) + b1.z*b1.z) + b1.w*b1.w;
        x2p[p] = pack2(xA, xB);
        best[2*p]   = __int_as_float(0x7f800000);
        best[2*p+1] = __int_as_float(0x7f800000);
        bidx[2*p] = 0; bidx[2*p+1] = 0;
    }

    const u64 NEG2 = pack2(-2.0f, -2.0f);
    const int s0 = warp * CPW;

    // ---- main scan ----
    #pragma unroll 1
    for (int t = 0; t < CPW; t++) {
        const int s = s0 + t;
        const ulonglong2 q0 = sm->cdup[4*s+0];
        const ulonglong2 q1 = sm->cdup[4*s+1];
        const ulonglong2 q2 = sm->cdup[4*s+2];
        const ulonglong2 q3 = sm->cdup[4*s+3];
        const ulonglong2 mt = sm->meta[s];
        float Lv, Lh; unpack2(Lv, Lh, mt.y);
        #pragma unroll
        for (int p = 0; p < NPAIR; p++) {
            u64 xc = mul2(xp[p][0], q0.x);
            xc = fma2(xp[p][1], q0.y, xc);
            xc = fma2(xp[p][2], q1.x, xc);
            xc = fma2(xp[p][3], q1.y, xc);
            xc = fma2(xp[p][4], q2.x, xc);
            xc = fma2(xp[p][5], q2.y, xc);
            xc = fma2(xp[p][6], q3.x, xc);
            xc = fma2(xp[p][7], q3.y, xc);
            u64 d2 = fma2(NEG2, xc, x2p[p]);
            d2 = add2(d2, mt.x);
            float lo, hi; unpack2(lo, hi, d2);
            float vlo = sqrt_approx(fmaxf(lo, 0.0f)) + Lv;
            float vhi = sqrt_approx(fmaxf(hi, 0.0f)) + Lv;
            if (vlo < best[2*p])   { best[2*p]   = vlo; bidx[2*p]   = s; }
            if (vhi < best[2*p+1]) { best[2*p+1] = vhi; bidx[2*p+1] = s; }
        }
    }

    // ---- cross-warp argmin reduce (ascending warp order == ascending s) ----
    #pragma unroll
    for (int p = 0; p < NPAIR; p++) {
        sm->red[warp * ROWS + (2*p)*32 + lane] =
            make_float2(best[2*p],   __int_as_float(bidx[2*p]));
        sm->red[warp * ROWS + (2*p+1)*32 + lane] =
            make_float2(best[2*p+1], __int_as_float(bidx[2*p+1]));
    }
    __syncthreads();

    float p2sel;
    {
        float bc = __int_as_float(0x7f800000);
        int   bi = 0;
        #pragma unroll
        for (int w = 0; w < NW; w++) {
            float2 c = sm->red[w * ROWS + tid];
            int ci = __float_as_int(c.y);
            if (c.x < bc) { bc = c.x; bi = ci; }   // strict <: keeps lowest s
        }
        const int grow = rowBase + tid;
        // x_hat from duplicated codebook (lower lane of each pair = exact value)
        ulonglong2 e0 = sm->cdup[4*bi+0];
        ulonglong2 e1 = sm->cdup[4*bi+1];
        ulonglong2 e2 = sm->cdup[4*bi+2];
        ulonglong2 e3 = sm->cdup[4*bi+3];
        float h0,h1,h2,h3,h4,h5,h6,h7,dmy;
        unpack2(h0, dmy, e0.x); unpack2(h1, dmy, e0.y);
        unpack2(h2, dmy, e1.x); unpack2(h3, dmy, e1.y);
        unpack2(h4, dmy, e2.x); unpack2(h5, dmy, e2.y);
        unpack2(h6, dmy, e3.x); unpack2(h7, dmy, e3.y);
        float4* op = reinterpret_cast<float4*>(
            out + (size_t)grow * (CBN * CDIM) + cb * CDIM);
        op[0] = make_float4(h0, h1, h2, h3);
        op[1] = make_float4(h4, h5, h6, h7);
        out[(size_t)B * (CBN * CDIM) + 1 + (size_t)grow * CBN + cb] = (float)bi;
        p2sel = sm->p2sh[bi];
    }

    // ---- per-CTA deterministic bits partial (double tree) ----
    __syncthreads();
    double* bs = reinterpret_cast<double*>(sm->red);
    bs[tid] = (double)p2sel;
    __syncthreads();
    #pragma unroll
    for (int off = 128; off > 0; off >>= 1) {
        if (tid < off) bs[tid] += bs[tid + off];
        __syncthreads();
    }
    if (tid == 0)
        g_part[blockIdx.x * gridDim.y + blockIdx.y] = bs[0];
}

// final deterministic sum over per-CTA partials
__global__ void __launch_bounds__(256) bits_final(float* __restrict__ out_bits, int n)
{
    __shared__ double sd[256];
    double acc = 0.0;
    for (int i = threadIdx.x; i < n; i += 256)
        acc += g_part[i];
    sd[threadIdx.x] = acc;
    __syncthreads();
    #pragma unroll
    for (int off = 128; off > 0; off >>= 1) {
        if (threadIdx.x < off) sd[threadIdx.x] += sd[threadIdx.x + off];
        __syncthreads();
    }
    if (threadIdx.x == 0) *out_bits = (float)sd[0];
}

extern "C" void kernel_launch(void* const* d_in, const int* in_sizes, int n_in,
                              void* d_out, int out_size)
{
    const float* x = nullptr;
    const float* codebook = nullptr;
    const float* logits = nullptr;
    int B = 0;
    for (int i = 0; i < n_in; i++) {
        if (in_sizes[i] == CBN * CSZ)             logits   = (const float*)d_in[i];
        else if (in_sizes[i] == CBN * CSZ * CDIM) codebook = (const float*)d_in[i];
        else { x = (const float*)d_in[i]; B = in_sizes[i] / (CBN * CDIM); }
    }
    float* out = (float*)d_out;

    size_t smem = sizeof(Smem);
    cudaFuncSetAttribute(ecvq_kernel,
                         cudaFuncAttributeMaxDynamicSharedMemorySize, (int)smem);

    int tilesY = B / ROWS;
    dim3 grid(CBN, tilesY);
    ecvq_kernel<<<grid, TPB, smem>>>(x, codebook, logits, out, B);
    bits_final<<<1, 256>>>(out + (size_t)B * (CBN * CDIM), CBN * tilesY);
}

// round 3
// speedup vs baseline: 1.5682x; 1.0021x over previous
#include <cuda_runtime.h>
#include <math.h>

#define CBN   6
#define CSZ   1024
#define CDIM  8
#define TPB   256
#define NW    8
#define CPW   (CSZ / NW)     // 128 candidates per warp
#define NPAIR 4              // row pairs per thread (8 rows)
#define ROWS  256            // rows per CTA

typedef unsigned long long u64;

// per-CTA double partial sums for deterministic bits reduction
__device__ double g_part[128 * CBN];

struct Smem {
    ulonglong2 cdup[CSZ * 4];   // 64KB: per s, dims (k,k+1) duplicated: ((ck,ck),(ck+1,ck+1))
    ulonglong2 meta[CSZ];       // 16KB: ((c2,c2),(L,L))
    float      p2sh[CSZ];       //  4KB: log2_pmf per candidate
    float      xsh[ROWS * CDIM];//  8KB
    float2     red[NW * ROWS];  // 16KB: cross-warp argmin partials (also reused scratch)
};

__device__ __forceinline__ u64 pack2(float lo, float hi) {
    u64 r; asm("mov.b64 %0, {%1,%2};" : "=l"(r) : "f"(lo), "f"(hi)); return r;
}
__device__ __forceinline__ void unpack2(float& lo, float& hi, u64 v) {
    asm("mov.b64 {%0,%1}, %2;" : "=f"(lo), "=f"(hi) : "l"(v));
}
__device__ __forceinline__ u64 mul2(u64 a, u64 b) {
    u64 d; asm("mul.rn.f32x2 %0, %1, %2;" : "=l"(d) : "l"(a), "l"(b)); return d;
}
__device__ __forceinline__ u64 add2(u64 a, u64 b) {
    u64 d; asm("add.rn.f32x2 %0, %1, %2;" : "=l"(d) : "l"(a), "l"(b)); return d;
}
__device__ __forceinline__ u64 fma2(u64 a, u64 b, u64 c) {
    u64 d; asm("fma.rn.f32x2 %0, %1, %2, %3;" : "=l"(d) : "l"(a), "l"(b), "l"(c)); return d;
}
__device__ __forceinline__ float sqrt_approx(float v) {
    float r; asm("sqrt.approx.f32 %0, %1;" : "=f"(r) : "f"(v)); return r;
}

__global__ void __launch_bounds__(TPB, 2) ecvq_kernel(
    const float* __restrict__ x,
    const float* __restrict__ codebook,
    const float* __restrict__ logits,
    float* __restrict__ out,
    int B)
{
    extern __shared__ unsigned char smem_raw[];
    Smem* sm = reinterpret_cast<Smem*>(smem_raw);

    const int tid     = threadIdx.x;
    const int cb      = blockIdx.x;
    const int rowBase = blockIdx.y * ROWS;
    float* scratch = reinterpret_cast<float*>(sm->red);

    // ---- log-softmax over logits[cb][:] ----
    float4 lv = *reinterpret_cast<const float4*>(logits + (size_t)cb * CSZ + tid * 4);
    float lm = fmaxf(fmaxf(lv.x, lv.y), fmaxf(lv.z, lv.w));
    scratch[tid] = lm; __syncthreads();
    #pragma unroll
    for (int off = 128; off > 0; off >>= 1) {
        if (tid < off) scratch[tid] = fmaxf(scratch[tid], scratch[tid + off]);
        __syncthreads();
    }
    const float m = scratch[0]; __syncthreads();
    float es = expf(lv.x - m) + expf(lv.y - m) + expf(lv.z - m) + expf(lv.w - m);
    scratch[tid] = es; __syncthreads();
    #pragma unroll
    for (int off = 128; off > 0; off >>= 1) {
        if (tid < off) scratch[tid] += scratch[tid + off];
        __syncthreads();
    }
    const float lnS = logf(scratch[0]); __syncthreads();

    // ---- stage codebook slice (duplicated for packed math) ----
    const float INV_LOG2 = 1.4426950408889634f;
    #pragma unroll
    for (int j = 0; j < 4; j++) {
        int s = tid * 4 + j;
        const float4* cp = reinterpret_cast<const float4*>(
            codebook + ((size_t)cb * CSZ + s) * CDIM);
        float4 c0 = cp[0], c1 = cp[1];
        float q0 = c0.x*c0.x, q1 = c0.y*c0.y, q2 = c0.z*c0.z, q3 = c0.w*c0.w;
        float q4 = c1.x*c1.x, q5 = c1.y*c1.y, q6 = c1.z*c1.z, q7 = c1.w*c1.w;
        float c2 = ((((((q0 + q1) + q2) + q3) + q4) + q5) + q6) + q7;
        float v  = (j == 0) ? lv.x : (j == 1) ? lv.y : (j == 2) ? lv.z : lv.w;
        float p2 = ((v - m) - lnS) * (-INV_LOG2);   // log2_pmf
        float L  = p2 / 0.005f;
        sm->cdup[4*s+0] = make_ulonglong2(pack2(c0.x, c0.x), pack2(c0.y, c0.y));
        sm->cdup[4*s+1] = make_ulonglong2(pack2(c0.z, c0.z), pack2(c0.w, c0.w));
        sm->cdup[4*s+2] = make_ulonglong2(pack2(c1.x, c1.x), pack2(c1.y, c1.y));
        sm->cdup[4*s+3] = make_ulonglong2(pack2(c1.z, c1.z), pack2(c1.w, c1.w));
        sm->meta[s]     = make_ulonglong2(pack2(c2, c2), pack2(L, L));
        sm->p2sh[s]     = p2;
    }

    // ---- stage x tile ----
    {
        int row = rowBase + tid;
        const float4* xp = reinterpret_cast<const float4*>(
            x + (size_t)row * (CBN * CDIM) + cb * CDIM);
        float4 p0 = xp[0], p1 = xp[1];
        float4* d = reinterpret_cast<float4*>(&sm->xsh[tid * CDIM]);
        d[0] = p0; d[1] = p1;
    }
    __syncthreads();

    // ---- per-thread registers: 4 row-pairs (8 rows), packed ----
    const int lane = tid & 31, warp = tid >> 5;
    u64   xp[NPAIR][CDIM];
    u64   x2p[NPAIR];
    float best[2 * NPAIR];
    int   bidx[2 * NPAIR];
    #pragma unroll
    for (int p = 0; p < NPAIR; p++) {
        int rA = (2 * p) * 32 + lane;
        int rB = rA + 32;
        const float4* pa = reinterpret_cast<const float4*>(&sm->xsh[rA * CDIM]);
        const float4* pb = reinterpret_cast<const float4*>(&sm->xsh[rB * CDIM]);
        float4 a0 = pa[0], a1 = pa[1];
        float4 b0 = pb[0], b1 = pb[1];
        xp[p][0] = pack2(a0.x, b0.x); xp[p][1] = pack2(a0.y, b0.y);
        xp[p][2] = pack2(a0.z, b0.z); xp[p][3] = pack2(a0.w, b0.w);
        xp[p][4] = pack2(a1.x, b1.x); xp[p][5] = pack2(a1.y, b1.y);
        xp[p][6] = pack2(a1.z, b1.z); xp[p][7] = pack2(a1.w, b1.w);
        float xA = ((((((a0.x*a0.x + a0.y*a0.y) + a0.z*a0.z) + a0.w*a0.w)
                      + a1.x*a1.x) + a1.y*a1.y) + a1.z*a1.z) + a1.w*a1.w;
        float xB = ((((((b0.x*b0.x + b0.y*b0.y) + b0.z*b0.z) + b0.w*b0.w)
                      + b1.x*b1.x) + b1.y*b1.y) + b1.z*b1.z) + b1.w*b1.w;
        x2p[p] = pack2(xA, xB);
        best[2*p]   = __int_as_float(0x7f800000);
        best[2*p+1] = __int_as_float(0x7f800000);
        bidx[2*p] = 0; bidx[2*p+1] = 0;
    }

    const u64 NEG2 = pack2(-2.0f, -2.0f);
    const int s0 = warp * CPW;

    // ---- main scan ----
    #pragma unroll 1
    for (int t = 0; t < CPW; t++) {
        const int s = s0 + t;
        const ulonglong2 q0 = sm->cdup[4*s+0];
        const ulonglong2 q1 = sm->cdup[4*s+1];
        const ulonglong2 q2 = sm->cdup[4*s+2];
        const ulonglong2 q3 = sm->cdup[4*s+3];
        const ulonglong2 mt = sm->meta[s];
        float Lv, Lh; unpack2(Lv, Lh, mt.y);
        #pragma unroll
        for (int p = 0; p < NPAIR; p++) {
            u64 xc = mul2(xp[p][0], q0.x);
            xc = fma2(xp[p][1], q0.y, xc);
            xc = fma2(xp[p][2], q1.x, xc);
            xc = fma2(xp[p][3], q1.y, xc);
            xc = fma2(xp[p][4], q2.x, xc);
            xc = fma2(xp[p][5], q2.y, xc);
            xc = fma2(xp[p][6], q3.x, xc);
            xc = fma2(xp[p][7], q3.y, xc);
            u64 d2 = fma2(NEG2, xc, x2p[p]);
            d2 = add2(d2, mt.x);
            float lo, hi; unpack2(lo, hi, d2);
            float vlo = sqrt_approx(fmaxf(lo, 0.0f)) + Lv;
            float vhi = sqrt_approx(fmaxf(hi, 0.0f)) + Lv;
            if (vlo < best[2*p])   { best[2*p]   = vlo; bidx[2*p]   = s; }
            if (vhi < best[2*p+1]) { best[2*p+1] = vhi; bidx[2*p+1] = s; }
        }
    }

    // ---- cross-warp argmin reduce (ascending warp order == ascending s) ----
    #pragma unroll
    for (int p = 0; p < NPAIR; p++) {
        sm->red[warp * ROWS + (2*p)*32 + lane] =
            make_float2(best[2*p],   __int_as_float(bidx[2*p]));
        sm->red[warp * ROWS + (2*p+1)*32 + lane] =
            make_float2(best[2*p+1], __int_as_float(bidx[2*p+1]));
    }
    __syncthreads();

    float p2sel;
    {
        float bc = __int_as_float(0x7f800000);
        int   bi = 0;
        #pragma unroll
        for (int w = 0; w < NW; w++) {
            float2 c = sm->red[w * ROWS + tid];
            int ci = __float_as_int(c.y);
            if (c.x < bc) { bc = c.x; bi = ci; }   // strict <: keeps lowest s
        }
        const int grow = rowBase + tid;
        // x_hat from duplicated codebook (lower lane of each pair = exact value)
        ulonglong2 e0 = sm->cdup[4*bi+0];
        ulonglong2 e1 = sm->cdup[4*bi+1];
        ulonglong2 e2 = sm->cdup[4*bi+2];
        ulonglong2 e3 = sm->cdup[4*bi+3];
        float h0,h1,h2,h3,h4,h5,h6,h7,dmy;
        unpack2(h0, dmy, e0.x); unpack2(h1, dmy, e0.y);
        unpack2(h2, dmy, e1.x); unpack2(h3, dmy, e1.y);
        unpack2(h4, dmy, e2.x); unpack2(h5, dmy, e2.y);
        unpack2(h6, dmy, e3.x); unpack2(h7, dmy, e3.y);
        float4* op = reinterpret_cast<float4*>(
            out + (size_t)grow * (CBN * CDIM) + cb * CDIM);
        op[0] = make_float4(h0, h1, h2, h3);
        op[1] = make_float4(h4, h5, h6, h7);
        out[(size_t)B * (CBN * CDIM) + 1 + (size_t)grow * CBN + cb] = (float)bi;
        p2sel = sm->p2sh[bi];
    }

    // ---- per-CTA deterministic bits partial (double tree) ----
    __syncthreads();
    double* bs = reinterpret_cast<double*>(sm->red);
    bs[tid] = (double)p2sel;
    __syncthreads();
    #pragma unroll
    for (int off = 128; off > 0; off >>= 1) {
        if (tid < off) bs[tid] += bs[tid + off];
        __syncthreads();
    }
    if (tid == 0)
        g_part[blockIdx.x * gridDim.y + blockIdx.y] = bs[0];
}

// final deterministic sum over per-CTA partials
__global__ void __launch_bounds__(256) bits_final(float* __restrict__ out_bits, int n)
{
    __shared__ double sd[256];
    double acc = 0.0;
    for (int i = threadIdx.x; i < n; i += 256)
        acc += g_part[i];
    sd[threadIdx.x] = acc;
    __syncthreads();
    #pragma unroll
    for (int off = 128; off > 0; off >>= 1) {
        if (threadIdx.x < off) sd[threadIdx.x] += sd[threadIdx.x + off];
        __syncthreads();
    }
    if (threadIdx.x == 0) *out_bits = (float)sd[0];
}

extern "C" void kernel_launch(void* const* d_in, const int* in_sizes, int n_in,
                              void* d_out, int out_size)
{
    const float* x = nullptr;
    const float* codebook = nullptr;
    const float* logits = nullptr;
    int B = 0;
    for (int i = 0; i < n_in; i++) {
        if (in_sizes[i] == CBN * CSZ)             logits   = (const float*)d_in[i];
        else if (in_sizes[i] == CBN * CSZ * CDIM) codebook = (const float*)d_in[i];
        else { x = (const float*)d_in[i]; B = in_sizes[i] / (CBN * CDIM); }
    }
    float* out = (float*)d_out;

    size_t smem = sizeof(Smem);
    cudaFuncSetAttribute(ecvq_kernel,
                         cudaFuncAttributeMaxDynamicSharedMemorySize, (int)smem);

    int tilesY = B / ROWS;
    dim3 grid(CBN, tilesY);
    ecvq_kernel<<<grid, TPB, smem>>>(x, codebook, logits, out, B);
    bits_final<<<1, 256>>>(out + (size_t)B * (CBN * CDIM), CBN * tilesY);
}